// round 6
// baseline (speedup 1.0000x reference)
#include <cuda_runtime.h>
#include <cuda_bf16.h>
#include <cstdint>

#define BB 2
#define QQ 300
#define TT 300
#define HH 256
#define WW 256
#define PP 12544
#define SPLITK 28
#define KC (PP / SPLITK)     // 448
#define KITERS (KC / 64)     // 7
#define NTM 5                // ceil(300/64)  (q tiles)
#define NTN 3                // ceil(300/128) (t tiles)

#define NTY 8
#define TROWS 32
#define PPT 49               // 256*49 = 12544

// padded sample tile: rows -1..32 (34), cols -1..256 (258)
#define SROW 258

// ---------------- scratch ----------------
__device__ __nv_bfloat16 g_om[(size_t)BB * QQ * PP];
__device__ __nv_bfloat16 g_s [(size_t)BB * QQ * PP];
__device__ __nv_bfloat16 g_tm[(size_t)BB * TT * PP];
__device__ float g_negsum[BB * QQ];
__device__ float g_ssum [BB * QQ];
__device__ float g_tmsum [BB * TT];
__device__ float g_D1p[(size_t)SPLITK * BB * QQ * TT];
__device__ float g_D2p[(size_t)SPLITK * BB * QQ * TT];

__device__ float2 g_spt[(size_t)BB * PP];
__device__ int g_binstart[BB][NTY + 1];
__device__ float g_psA[BB * 600 * NTY];
__device__ float g_psB[BB * 600 * NTY];

__device__ __forceinline__ void cp16(uint32_t dst, const void* src, bool pred) {
    int sz = pred ? 16 : 0;
    asm volatile("cp.async.cg.shared.global [%0], [%1], 16, %2;"
                 :: "r"(dst), "l"(src), "r"(sz));
}

// ---------------- kernel 0: counting sort; one CTA per (batch, bin) ----------------
__global__ __launch_bounds__(256) void bin_kernel(const float* __restrict__ point_coords)
{
    int b = blockIdx.x >> 3;
    int kbin = blockIdx.x & 7;
    int tid = threadIdx.x;
    int lane = tid & 31, warp = tid >> 5;
    const float2* pc = (const float2*)(point_coords + (size_t)b * PP * 2);

    __shared__ int hist[256 * NTY];
    __shared__ int total[NTY];
    __shared__ int s_base;

    int cnt[NTY];
    #pragma unroll
    for (int k = 0; k < NTY; k++) cnt[k] = 0;

    int start = tid * PPT;
    for (int j = 0; j < PPT; j++) {
        float2 pt = pc[start + j];
        float y = pt.y * (float)HH - 0.5f;
        int y0 = (int)floorf(y);
        int t = min(max(y0, 0), HH - 1) >> 5;
        cnt[t]++;
    }
    #pragma unroll
    for (int k = 0; k < NTY; k++) hist[tid * NTY + k] = cnt[k];
    __syncthreads();

    // warp w reduces bin w's total (8 warps)
    int w = warp;
    {
        int s = 0;
        #pragma unroll
        for (int i = 0; i < 8; i++) s += hist[(lane * 8 + i) * NTY + w];
        #pragma unroll
        for (int o = 16; o > 0; o >>= 1) s += __shfl_down_sync(0xffffffffu, s, o);
        if (lane == 0) total[w] = s;
    }
    __syncthreads();

    if (tid == 0) {
        int base = 0;
        for (int k = 0; k < kbin; k++) base += total[k];
        s_base = base;
        g_binstart[b][kbin] = base;
        if (kbin == NTY - 1) g_binstart[b][NTY] = PP;
    }

    // warp 0: exclusive scan over 256 thread-counts of bin kbin (8 per lane)
    if (warp == 0) {
        int v[8], pre[8], run = 0;
        #pragma unroll
        for (int i = 0; i < 8; i++) {
            v[i] = hist[(lane * 8 + i) * NTY + kbin];
            pre[i] = run; run += v[i];
        }
        int x = run;
        #pragma unroll
        for (int o = 1; o < 32; o <<= 1) {
            int y = __shfl_up_sync(0xffffffffu, x, o);
            if (lane >= o) x += y;
        }
        int excl = x - run;
        #pragma unroll
        for (int i = 0; i < 8; i++) hist[(lane * 8 + i) * NTY + kbin] = excl + pre[i];
    }
    __syncthreads();

    int off = s_base + hist[tid * NTY + kbin];
    for (int j = 0; j < PPT; j++) {
        float2 pt = pc[start + j];
        float x = pt.x * (float)WW - 0.5f;
        float y = pt.y * (float)HH - 0.5f;
        int y0 = (int)floorf(y);
        int t = min(max(y0, 0), HH - 1) >> 5;
        if (t == kbin) {
            g_spt[(size_t)b * PP + off] = make_float2(x, y);
            off++;
        }
    }
}

// ---------------- kernel 1: tiled sampling, padded tile, lean inner loop ----------------
__global__ __launch_bounds__(256) void sample_kernel(
    const float* __restrict__ pred_masks,
    const float* __restrict__ tgt_masks)
{
    int bx = blockIdx.x;
    int tile = bx & (NTY - 1); bx >>= 3;
    int b = bx / 600;
    int r = bx % 600;
    bool is_pred = (r < 300);
    int m = is_pred ? r : r - 300;

    const float* mask = (is_pred ? pred_masks : tgt_masks) + ((size_t)(b * 300 + m)) * (HH * WW);
    size_t obase = (size_t)(b * 300 + m) * PP;

    __shared__ float sm[34 * SROW];   // rows ly=-1..32, cols x=-1..256

    int tid = threadIdx.x;
    int row0 = tile * TROWS;

    // zero the guard borders (cols -1 & 256 every row; top row if tile0; bottom row if tile7)
    for (int i = tid; i < 34; i += 256) {
        sm[i * SROW + 0] = 0.f;
        sm[i * SROW + 257] = 0.f;
    }
    if (tile == 0) {
        for (int i = tid; i < 256; i += 256) sm[1 + i] = 0.f;          // row ly=-1
    }
    if (tile == NTY - 1) {
        for (int i = tid; i < 256; i += 256) sm[33 * SROW + 1 + i] = 0.f;  // row ly=32
    }

    // stage rows (32 rows + bottom halo when present), scalar coalesced
    int nrows = (tile == NTY - 1) ? TROWS : (TROWS + 1);
    for (int i = tid; i < nrows * WW; i += 256) {
        int row = i >> 8;
        int c = i & 255;
        sm[(row + 1) * SROW + 1 + c] = __ldg(mask + (size_t)(row0 + row) * WW + c);
    }

    int pbeg = g_binstart[b][tile];
    int pend = g_binstart[b][tile + 1];
    __syncthreads();

    float s0 = 0.f, s1 = 0.f;
    const float2* spt = g_spt + (size_t)b * PP;
    // base pointer so that index = (ly0+1)*SROW + (x0+1)
    const float* smb = sm;

    for (int j = pbeg + tid; j < pend; j += 256) {
        float2 pt = spt[j];
        float x = pt.x, y = pt.y;
        float x0f = floorf(x), y0f = floorf(y);
        float wx = x - x0f, wy = y - y0f;
        int x0 = (int)x0f, y0 = (int)y0f;

        int a00 = (y0 - row0 + 1) * SROW + (x0 + 1);
        float f00 = smb[a00];
        float f01 = smb[a00 + 1];
        float f10 = smb[a00 + SROW];
        float f11 = smb[a00 + SROW + 1];

        float top = f00 + wx * (f01 - f00);
        float bot = f10 + wx * (f11 - f10);
        float om = top + wy * (bot - top);

        if (is_pred) {
            float e = __expf(-fabsf(om));
            float den = 1.f + e;
            float rc = __fdividef(1.f, den);
            float sg = (om >= 0.f) ? rc : e * rc;
            float sp = fmaxf(om, 0.f) + __logf(den);   // softplus(om)
            g_om[obase + j] = __float2bfloat16(om);
            g_s [obase + j] = __float2bfloat16(sg);
            s0 += sp;
            s1 += sg;
        } else {
            g_tm[obase + j] = __float2bfloat16(om);
            s0 += om;
        }
    }

    #pragma unroll
    for (int o = 16; o > 0; o >>= 1) {
        s0 += __shfl_down_sync(0xffffffffu, s0, o);
        s1 += __shfl_down_sync(0xffffffffu, s1, o);
    }
    __shared__ float rs0[8], rs1[8];
    int lane = tid & 31, warp = tid >> 5;
    if (lane == 0) { rs0[warp] = s0; rs1[warp] = s1; }
    __syncthreads();
    if (tid == 0) {
        float t0 = 0.f, t1 = 0.f;
        #pragma unroll
        for (int i = 0; i < 8; i++) { t0 += rs0[i]; t1 += rs1[i]; }
        int idx = (b * 600 + r) * NTY + tile;
        g_psA[idx] = t0;
        g_psB[idx] = t1;
    }
}

// ---------------- kernel 1b ----------------
__global__ void reduce_sums_kernel()
{
    int idx = blockIdx.x * 256 + threadIdx.x;
    if (idx >= BB * 600) return;
    int b = idx / 600, r = idx % 600;
    float a = 0.f, c = 0.f;
    #pragma unroll
    for (int k = 0; k < NTY; k++) {
        a += g_psA[idx * NTY + k];
        c += g_psB[idx * NTY + k];
    }
    if (r < 300) {
        g_negsum[b * 300 + r] = a;
        g_ssum [b * 300 + r] = c;
    } else {
        g_tmsum[b * 300 + (r - 300)] = a;
    }
}

// ---------------- mma helpers ----------------
__device__ __forceinline__ void ldsm_x4_a(uint32_t* r, uint32_t a) {
    asm volatile("ldmatrix.sync.aligned.m8n8.x4.shared.b16 {%0,%1,%2,%3}, [%4];"
                 : "=r"(r[0]), "=r"(r[1]), "=r"(r[2]), "=r"(r[3]) : "r"(a));
}
__device__ __forceinline__ void mma16816(float* d, const uint32_t* a, const uint32_t* b) {
    asm volatile("mma.sync.aligned.m16n8k16.row.col.f32.bf16.bf16.f32 "
                 "{%0,%1,%2,%3}, {%4,%5,%6,%7}, {%8,%9}, {%0,%1,%2,%3};"
                 : "+f"(d[0]), "+f"(d[1]), "+f"(d[2]), "+f"(d[3])
                 : "r"(a[0]), "r"(a[1]), "r"(a[2]), "r"(a[3]), "r"(b[0]), "r"(b[1]));
}
__device__ __forceinline__ uint32_t sw_off(int row, int col_e) {
    int chunk = col_e >> 3;
    return (uint32_t)(row * 128 + ((chunk ^ (row & 7)) << 4));
}

// ---------------- kernel 2: dual bf16 GEMM, 64x128 CTA tile ----------------
#define STAGE_BYTES 32768   // A_om 8K | A_s 8K | B 16K

__global__ __launch_bounds__(256) void gemm_kernel()
{
    int bx = blockIdx.x;
    int split = bx % SPLITK; bx /= SPLITK;
    int tn = bx % NTN; bx /= NTN;
    int tm = bx % NTM;
    int b  = bx / NTM;
    int m0 = tm * 64, n0 = tn * 128;

    __shared__ __align__(16) unsigned char smem[2][STAGE_BYTES];
    uint32_t smem_base = (uint32_t)__cvta_generic_to_shared(&smem[0][0]);

    int tid = threadIdx.x;
    int warp = tid >> 5, lane = tid & 31;
    int wm0 = (warp >> 2) * 32;
    int wn0 = (warp & 3) * 32;

    float acc1[2][4][4];
    float acc2[2][4][4];
    #pragma unroll
    for (int i = 0; i < 2; i++)
        #pragma unroll
        for (int j = 0; j < 4; j++)
            #pragma unroll
            for (int k = 0; k < 4; k++) { acc1[i][j][k] = 0.f; acc2[i][j][k] = 0.f; }

    const __nv_bfloat16* Aom = g_om + (size_t)(b * 300) * PP;
    const __nv_bfloat16* As  = g_s  + (size_t)(b * 300) * PP;
    const __nv_bfloat16* Btm = g_tm + (size_t)(b * 300) * PP;

    int kbase = split * KC;

    auto load_stage = [&](int kt, int st) {
        int k0 = kbase + kt * 64;
        #pragma unroll
        for (int u = 0; u < 8; ++u) {
            int i = tid + u * 256;
            int a = i >> 9;
            uint32_t dst;
            const void* src;
            bool pred;
            if (a < 2) {
                int rem = i & 511;
                int row = rem >> 3;
                int ch = rem & 7;
                int g = m0 + row;
                pred = (g < 300);
                const __nv_bfloat16* base = a ? As : Aom;
                src = base + (size_t)min(g, 299) * PP + k0 + ch * 8;
                dst = smem_base + (uint32_t)(st * STAGE_BYTES + a * 8192) + sw_off(row, ch * 8);
            } else {
                int rem = i - 1024;
                int row = rem >> 3;
                int ch = rem & 7;
                int g = n0 + row;
                pred = (g < 300);
                src = Btm + (size_t)min(g, 299) * PP + k0 + ch * 8;
                dst = smem_base + (uint32_t)(st * STAGE_BYTES + 16384) + sw_off(row, ch * 8);
            }
            cp16(dst, src, pred);
        }
        asm volatile("cp.async.commit_group;" ::: "memory");
    };

    load_stage(0, 0);

    for (int kt = 0; kt < KITERS; ++kt) {
        int st = kt & 1;
        if (kt + 1 < KITERS) {
            load_stage(kt + 1, (kt + 1) & 1);
            asm volatile("cp.async.wait_group 1;" ::: "memory");
        } else {
            asm volatile("cp.async.wait_group 0;" ::: "memory");
        }
        __syncthreads();

        uint32_t base_om = smem_base + (uint32_t)(st * STAGE_BYTES);
        uint32_t base_s  = base_om + 8192;
        uint32_t base_tm = base_om + 16384;

        #pragma unroll
        for (int ks = 0; ks < 4; ++ks) {
            uint32_t ao[2][4], av[2][4], bb[2][4];
            int arow = wm0 + (lane & 15);
            int acol = ks * 16 + (lane >> 4) * 8;
            #pragma unroll
            for (int ti = 0; ti < 2; ++ti) {
                ldsm_x4_a(ao[ti], base_om + sw_off(arow + ti * 16, acol));
                ldsm_x4_a(av[ti], base_s  + sw_off(arow + ti * 16, acol));
            }
            int mi = lane >> 3;
            int brow_base = wn0 + ((mi >> 1) * 8) + (lane & 7);
            int bcol = ks * 16 + (mi & 1) * 8;
            #pragma unroll
            for (int g2 = 0; g2 < 2; ++g2) {
                ldsm_x4_a(bb[g2], base_tm + sw_off(brow_base + g2 * 16, bcol));
            }
            #pragma unroll
            for (int ti = 0; ti < 2; ++ti)
                #pragma unroll
                for (int tn2 = 0; tn2 < 4; ++tn2) {
                    const uint32_t* bf = &bb[tn2 >> 1][(tn2 & 1) * 2];
                    mma16816(acc1[ti][tn2], ao[ti], bf);
                    mma16816(acc2[ti][tn2], av[ti], bf);
                }
        }
        __syncthreads();
    }

    float* D1 = g_D1p + ((size_t)(split * BB + b)) * (QQ * TT);
    float* D2 = g_D2p + ((size_t)(split * BB + b)) * (QQ * TT);
    #pragma unroll
    for (int ti = 0; ti < 2; ++ti)
        #pragma unroll
        for (int tn2 = 0; tn2 < 4; ++tn2)
            #pragma unroll
            for (int rh = 0; rh < 2; ++rh) {
                int q = m0 + wm0 + ti * 16 + (lane >> 2) + rh * 8;
                int t = n0 + wn0 + tn2 * 8 + (lane & 3) * 2;
                if (q < QQ && t < TT) {
                    float2 v1 = make_float2(acc1[ti][tn2][rh * 2 + 0], acc1[ti][tn2][rh * 2 + 1]);
                    float2 v2 = make_float2(acc2[ti][tn2][rh * 2 + 0], acc2[ti][tn2][rh * 2 + 1]);
                    *(float2*)&D1[q * TT + t] = v1;
                    *(float2*)&D2[q * TT + t] = v2;
                }
            }
}

// ---------------- kernel 3 ----------------
__global__ __launch_bounds__(256) void final_kernel(
    const float* __restrict__ pred_boxes,
    const float* __restrict__ tgt_boxes,
    float* __restrict__ out)
{
    int idx = blockIdx.x * 256 + threadIdx.x;
    if (idx >= BB * QQ * TT) return;
    int b = idx / (QQ * TT);
    int r = idx % (QQ * TT);
    int q = r / TT, t = r % TT;

    float D1 = 0.f, D2 = 0.f;
    #pragma unroll
    for (int s = 0; s < SPLITK; ++s) {
        size_t off = ((size_t)(s * BB + b)) * (QQ * TT) + r;
        D1 += g_D1p[off];
        D2 += g_D2p[off];
    }

    float ns = g_negsum[b * 300 + q];
    float ss = g_ssum [b * 300 + q];
    float ts = g_tmsum [b * 300 + t];

    float cost_mask = (ns - D1) * (1.f / (float)PP);
    float cost_dice = 1.f - (2.f * D2 + 1.f) / (ss + ts + 1.f);

    const float* pb = pred_boxes + (size_t)(b * 300 + q) * 4;
    const float* tb = tgt_boxes  + (size_t)(b * 300 + t) * 4;
    float p0 = pb[0], p1 = pb[1], p2 = pb[2], p3 = pb[3];
    float t0 = tb[0], t1 = tb[1], t2 = tb[2], t3 = tb[3];

    float cost_bbox = fabsf(p0 - t0) + fabsf(p1 - t1) + fabsf(p2 - t2) + fabsf(p3 - t3);

    float ax0 = p0 - 0.5f * p2, ay0 = p1 - 0.5f * p3;
    float ax1 = p0 + 0.5f * p2, ay1 = p1 + 0.5f * p3;
    float bx0 = t0 - 0.5f * t2, by0 = t1 - 0.5f * t3;
    float bx1 = t0 + 0.5f * t2, by1 = t1 + 0.5f * t3;

    float areaA = (ax1 - ax0) * (ay1 - ay0);
    float areaB = (bx1 - bx0) * (by1 - by0);
    float iw = fminf(ax1, bx1) - fmaxf(ax0, bx0);
    float ih = fminf(ay1, by1) - fmaxf(ay0, by0);
    iw = fmaxf(iw, 0.f); ih = fmaxf(ih, 0.f);
    float inter = iw * ih;
    float uni = areaA + areaB - inter;
    float iou = inter / uni;
    float ew = fmaxf(ax1, bx1) - fminf(ax0, bx0);
    float eh = fmaxf(ay1, by1) - fminf(ay0, by0);
    ew = fmaxf(ew, 0.f); eh = fmaxf(eh, 0.f);
    float ae = ew * eh;
    float giou = iou - (ae - uni) / ae;

    out[idx] = 5.f * cost_mask + 5.f * cost_dice + 5.f * cost_bbox - 2.f * giou;
}

// ---------------- launch ----------------
extern "C" void kernel_launch(void* const* d_in, const int* in_sizes, int n_in,
                              void* d_out, int out_size)
{
    const float* pred_masks   = (const float*)d_in[0];
    const float* tgt_masks    = (const float*)d_in[1];
    const float* pred_boxes   = (const float*)d_in[2];
    const float* tgt_boxes    = (const float*)d_in[3];
    const float* point_coords = (const float*)d_in[4];
    float* out = (float*)d_out;

    bin_kernel<<<BB * NTY, 256>>>(point_coords);
    sample_kernel<<<BB * 600 * NTY, 256>>>(pred_masks, tgt_masks);
    reduce_sums_kernel<<<(BB * 600 + 255) / 256, 256>>>();
    gemm_kernel<<<BB * NTM * NTN * SPLITK, 256>>>();
    final_kernel<<<(BB * QQ * TT + 255) / 256, 256>>>(pred_boxes, tgt_boxes, out);
}